// round 1
// baseline (speedup 1.0000x reference)
#include <cuda_runtime.h>
#include <cuda_bf16.h>

#define D_DIM 64
#define BT 32            // b-rows per block
#define NT 64            // n-cols per block
#define TPB 256
#define SROW 68          // smem row stride (floats): 16B-aligned, conflict-free

__global__ __launch_bounds__(TPB)
void wavelet_kernel(const float* __restrict__ x,
                    const float* __restrict__ centers,
                    const float* __restrict__ scales,
                    float* __restrict__ out,
                    int N)
{
    __shared__ float sx[BT * SROW];
    __shared__ float sa[NT * SROW];   // 1/s
    __shared__ float sb[NT * SROW];   // -c/s

    const int tid = threadIdx.x;
    const int b0 = blockIdx.x * BT;
    const int n0 = blockIdx.y * NT;

    // Load x tile (coalesced)
    #pragma unroll
    for (int i = tid; i < BT * D_DIM; i += TPB) {
        int r = i >> 6, c = i & 63;
        sx[r * SROW + c] = x[(b0 + r) * D_DIM + c];
    }
    // Load centers/scales tile, precompute a = 1/s, bb = -c/s
    #pragma unroll
    for (int i = tid; i < NT * D_DIM; i += TPB) {
        int r = i >> 6, c = i & 63;
        int g = (n0 + r) * D_DIM + c;
        float sc  = scales[g];
        float cc  = centers[g];
        float inv = 1.0f / sc;
        sa[r * SROW + c] = inv;
        sb[r * SROW + c] = -cc * inv;
    }
    __syncthreads();

    const int bl = tid >> 3;   // 0..31 : local b row
    const int ns = tid & 7;    // 0..7  : n sub-lane; handles n = ns + 8j

    float sacc[8], pacc[8];
    #pragma unroll
    for (int j = 0; j < 8; j++) { sacc[j] = 0.0f; pacc[j] = 1.0f; }

    #pragma unroll
    for (int d4 = 0; d4 < D_DIM; d4 += 4) {
        const float4 xv = *reinterpret_cast<const float4*>(&sx[bl * SROW + d4]);
        #pragma unroll
        for (int j = 0; j < 8; j++) {
            const int nl = ns + (j << 3);
            const float4 av = *reinterpret_cast<const float4*>(&sa[nl * SROW + d4]);
            const float4 bv = *reinterpret_cast<const float4*>(&sb[nl * SROW + d4]);
            float z, q;
            z = fmaf(xv.x, av.x, bv.x); q = z * z; sacc[j] += q; pacc[j] = fmaf(-q, pacc[j], pacc[j]);
            z = fmaf(xv.y, av.y, bv.y); q = z * z; sacc[j] += q; pacc[j] = fmaf(-q, pacc[j], pacc[j]);
            z = fmaf(xv.z, av.z, bv.z); q = z * z; sacc[j] += q; pacc[j] = fmaf(-q, pacc[j], pacc[j]);
            z = fmaf(xv.w, av.w, bv.w); q = z * z; sacc[j] += q; pacc[j] = fmaf(-q, pacc[j], pacc[j]);
        }
        // Range-control fold: keep |pacc| bounded (product alone can hit e^88 in the tail)
        if (d4 == 28) {
            #pragma unroll
            for (int j = 0; j < 8; j++) {
                pacc[j] *= __expf(-0.5f * sacc[j]);
                sacc[j] = 0.0f;
            }
        }
    }

    #pragma unroll
    for (int j = 0; j < 8; j++) {
        float h = pacc[j] * __expf(-0.5f * sacc[j]);
        out[(long)(b0 + bl) * N + (n0 + ns + (j << 3))] = h;
    }
}

extern "C" void kernel_launch(void* const* d_in, const int* in_sizes, int n_in,
                              void* d_out, int out_size)
{
    const float* x       = (const float*)d_in[0];
    const float* centers = (const float*)d_in[1];
    const float* scales  = (const float*)d_in[2];
    float* out = (float*)d_out;

    const int B = in_sizes[0] / D_DIM;   // 8192
    const int N = in_sizes[1] / D_DIM;   // 512

    dim3 grid(B / BT, N / NT);           // (256, 8)
    wavelet_kernel<<<grid, TPB>>>(x, centers, scales, out, N);
}

// round 2
// speedup vs baseline: 1.3720x; 1.3720x over previous
#include <cuda_runtime.h>
#include <cstdint>

#define D_DIM 64
#define BT 128           // b per block
#define NT 64            // n per block
#define TPB 256
#define XSTRIDE 68       // floats, 16B-aligned row stride
#define ASTRIDE 68

// ---- packed f32x2 helpers (Blackwell FFMA2 path) ----
__device__ __forceinline__ uint64_t pk2(float lo, float hi) {
    uint64_t r; asm("mov.b64 %0, {%1, %2};" : "=l"(r) : "f"(lo), "f"(hi)); return r;
}
__device__ __forceinline__ void upk2(uint64_t v, float& lo, float& hi) {
    asm("mov.b64 {%0, %1}, %2;" : "=f"(lo), "=f"(hi) : "l"(v));
}
__device__ __forceinline__ uint64_t fma2(uint64_t a, uint64_t b, uint64_t c) {
    uint64_t d; asm("fma.rn.f32x2 %0, %1, %2, %3;" : "=l"(d) : "l"(a), "l"(b), "l"(c)); return d;
}
__device__ __forceinline__ uint64_t mul2(uint64_t a, uint64_t b) {
    uint64_t d; asm("mul.rn.f32x2 %0, %1, %2;" : "=l"(d) : "l"(a), "l"(b)); return d;
}
__device__ __forceinline__ uint64_t add2(uint64_t a, uint64_t b) {
    uint64_t d; asm("add.rn.f32x2 %0, %1, %2;" : "=l"(d) : "l"(a), "l"(b)); return d;
}

extern __shared__ float smem_dyn[];

// Process 4 d-dims: each thread covers 4 b x 8 n (4 packed n-pairs).
__device__ __forceinline__ void do_dblk(const float* __restrict__ xrow,
                                        const float* __restrict__ arow,
                                        const float* __restrict__ brow,
                                        int dblk, uint64_t M1,
                                        uint64_t (&sacc)[4][4],
                                        uint64_t (&pacc)[4][4])
{
    float xq[4][4];
    #pragma unroll
    for (int bi = 0; bi < 4; bi++) {
        float4 v = *reinterpret_cast<const float4*>(xrow + bi * XSTRIDE + dblk);
        xq[bi][0] = v.x; xq[bi][1] = v.y; xq[bi][2] = v.z; xq[bi][3] = v.w;
    }
    #pragma unroll
    for (int dd = 0; dd < 4; dd++) {
        const int d = dblk + dd;
        const ulonglong2 a01 = *reinterpret_cast<const ulonglong2*>(arow + d * ASTRIDE);
        const ulonglong2 a23 = *reinterpret_cast<const ulonglong2*>(arow + d * ASTRIDE + 4);
        const ulonglong2 b01 = *reinterpret_cast<const ulonglong2*>(brow + d * ASTRIDE);
        const ulonglong2 b23 = *reinterpret_cast<const ulonglong2*>(brow + d * ASTRIDE + 4);
        const uint64_t A[4]  = {a01.x, a01.y, a23.x, a23.y};
        const uint64_t Bv[4] = {b01.x, b01.y, b23.x, b23.y};
        #pragma unroll
        for (int bi = 0; bi < 4; bi++) {
            const uint64_t xp = pk2(xq[bi][dd], xq[bi][dd]);
            #pragma unroll
            for (int k = 0; k < 4; k++) {
                uint64_t z = fma2(xp, A[k], Bv[k]);
                uint64_t w = fma2(z, z, M1);          // z^2 - 1 (sign cancels: even count)
                sacc[bi][k] = add2(sacc[bi][k], w);   // sum z^2 = sum w + count
                pacc[bi][k] = mul2(pacc[bi][k], w);
            }
        }
    }
}

__global__ __launch_bounds__(TPB, 2)
void wavelet_kernel(const float* __restrict__ x,
                    const float* __restrict__ centers,
                    const float* __restrict__ scales,
                    float* __restrict__ out, int N)
{
    float* sx = smem_dyn;                   // [BT][XSTRIDE]  b-major
    float* sa = sx + BT * XSTRIDE;          // [D][ASTRIDE]   d-major (transposed): 1/s
    float* sb = sa + D_DIM * ASTRIDE;       // [D][ASTRIDE]   -c/s

    const int tid = threadIdx.x;
    const int b0 = blockIdx.x * BT;
    const int n0 = blockIdx.y * NT;

    // x tile (coalesced)
    #pragma unroll 4
    for (int i = tid; i < BT * D_DIM; i += TPB) {
        int r = i >> 6, c = i & 63;
        sx[r * XSTRIDE + c] = x[(b0 + r) * D_DIM + c];
    }
    // a/b tiles, transposed to [d][n]
    #pragma unroll 4
    for (int i = tid; i < NT * D_DIM; i += TPB) {
        int d = i & 63, n = i >> 6;
        int g = (n0 + n) * D_DIM + d;
        float inv = 1.0f / scales[g];
        sa[d * ASTRIDE + n] = inv;
        sb[d * ASTRIDE + n] = -centers[g] * inv;
    }
    __syncthreads();

    const int ng = tid & 7;    // 8 n's at ng*8
    const int bg = tid >> 3;   // 4 b's at bg*4

    const float* xrow = sx + (bg * 4) * XSTRIDE;
    const float* arow = sa + ng * 8;
    const float* brow = sb + ng * 8;

    const uint64_t M1 = pk2(-1.0f, -1.0f);
    uint64_t sacc[4][4], pacc[4][4];
    #pragma unroll
    for (int bi = 0; bi < 4; bi++)
        #pragma unroll
        for (int k = 0; k < 4; k++) { sacc[bi][k] = pk2(0.f, 0.f); pacc[bi][k] = pk2(1.f, 1.f); }

    // first half: d = 0..31
    #pragma unroll 1
    for (int dblk = 0; dblk < 32; dblk += 4)
        do_dblk(xrow, arow, brow, dblk, M1, sacc, pacc);

    // range-control fold: apply Gaussian factor for first 32 dims
    #pragma unroll
    for (int bi = 0; bi < 4; bi++)
        #pragma unroll
        for (int k = 0; k < 4; k++) {
            float s0, s1, p0, p1;
            upk2(sacc[bi][k], s0, s1);
            upk2(pacc[bi][k], p0, p1);
            p0 *= __expf(-0.5f * (s0 + 32.0f));
            p1 *= __expf(-0.5f * (s1 + 32.0f));
            pacc[bi][k] = pk2(p0, p1);
            sacc[bi][k] = pk2(0.f, 0.f);
        }

    // second half: d = 32..63
    #pragma unroll 1
    for (int dblk = 32; dblk < 64; dblk += 4)
        do_dblk(xrow, arow, brow, dblk, M1, sacc, pacc);

    // epilogue
    float* orow = out + (long)(b0 + bg * 4) * N + n0 + ng * 8;
    #pragma unroll
    for (int bi = 0; bi < 4; bi++) {
        float h[8];
        #pragma unroll
        for (int k = 0; k < 4; k++) {
            float s0, s1, p0, p1;
            upk2(sacc[bi][k], s0, s1);
            upk2(pacc[bi][k], p0, p1);
            h[2 * k]     = p0 * __expf(-0.5f * (s0 + 32.0f));
            h[2 * k + 1] = p1 * __expf(-0.5f * (s1 + 32.0f));
        }
        float4 v0 = {h[0], h[1], h[2], h[3]};
        float4 v1 = {h[4], h[5], h[6], h[7]};
        *reinterpret_cast<float4*>(orow + (long)bi * N)     = v0;
        *reinterpret_cast<float4*>(orow + (long)bi * N + 4) = v1;
    }
}

extern "C" void kernel_launch(void* const* d_in, const int* in_sizes, int n_in,
                              void* d_out, int out_size)
{
    const float* x       = (const float*)d_in[0];
    const float* centers = (const float*)d_in[1];
    const float* scales  = (const float*)d_in[2];
    float* out = (float*)d_out;

    const int B = in_sizes[0] / D_DIM;   // 8192
    const int N = in_sizes[1] / D_DIM;   // 512

    const int smem_bytes = (BT * XSTRIDE + 2 * D_DIM * ASTRIDE) * sizeof(float); // 69632
    static bool attr_set = false;
    if (!attr_set) {
        cudaFuncSetAttribute(wavelet_kernel,
                             cudaFuncAttributeMaxDynamicSharedMemorySize, smem_bytes);
        attr_set = true;
    }

    dim3 grid(B / BT, N / NT);           // (64, 8)
    wavelet_kernel<<<grid, TPB, smem_bytes>>>(x, centers, scales, out, N);
}

// round 3
// speedup vs baseline: 1.4264x; 1.0396x over previous
#include <cuda_runtime.h>
#include <cstdint>

#define D_DIM 64
#define BT 64            // b per block
#define NT 64            // n per block
#define TPB 256
#define XSTRIDE 68       // floats; 16B-aligned row stride, conflict-free
#define ASTRIDE 68

// ---- packed f32x2 helpers (Blackwell FFMA2 path) ----
__device__ __forceinline__ uint64_t pk2(float lo, float hi) {
    uint64_t r; asm("mov.b64 %0, {%1, %2};" : "=l"(r) : "f"(lo), "f"(hi)); return r;
}
__device__ __forceinline__ void upk2(uint64_t v, float& lo, float& hi) {
    asm("mov.b64 {%0, %1}, %2;" : "=f"(lo), "=f"(hi) : "l"(v));
}
__device__ __forceinline__ uint64_t fma2(uint64_t a, uint64_t b, uint64_t c) {
    uint64_t d; asm("fma.rn.f32x2 %0, %1, %2, %3;" : "=l"(d) : "l"(a), "l"(b), "l"(c)); return d;
}
__device__ __forceinline__ uint64_t mul2(uint64_t a, uint64_t b) {
    uint64_t d; asm("mul.rn.f32x2 %0, %1, %2;" : "=l"(d) : "l"(a), "l"(b)); return d;
}
__device__ __forceinline__ uint64_t add2(uint64_t a, uint64_t b) {
    uint64_t d; asm("add.rn.f32x2 %0, %1, %2;" : "=l"(d) : "l"(a), "l"(b)); return d;
}

extern __shared__ float smem_dyn[];

// One 4-dim block: each thread covers 4 b x 4 n (2 packed n-pairs).
__device__ __forceinline__ void do_dblk(const float* __restrict__ xrow,
                                        const float* __restrict__ arow,
                                        const float* __restrict__ brow,
                                        int dblk, uint64_t M1,
                                        uint64_t (&sacc)[4][2],
                                        uint64_t (&pacc)[4][2])
{
    float xq[4][4];
    #pragma unroll
    for (int bi = 0; bi < 4; bi++) {
        float4 v = *reinterpret_cast<const float4*>(xrow + bi * XSTRIDE + dblk);
        xq[bi][0] = v.x; xq[bi][1] = v.y; xq[bi][2] = v.z; xq[bi][3] = v.w;
    }
    #pragma unroll
    for (int dd = 0; dd < 4; dd++) {
        const int d = dblk + dd;
        const ulonglong2 av = *reinterpret_cast<const ulonglong2*>(arow + d * ASTRIDE);
        const ulonglong2 bv = *reinterpret_cast<const ulonglong2*>(brow + d * ASTRIDE);
        const uint64_t A[2]  = {av.x, av.y};
        const uint64_t Bv[2] = {bv.x, bv.y};
        #pragma unroll
        for (int bi = 0; bi < 4; bi++) {
            const uint64_t xp = pk2(xq[bi][dd], xq[bi][dd]);
            #pragma unroll
            for (int k = 0; k < 2; k++) {
                uint64_t z = fma2(xp, A[k], Bv[k]);
                uint64_t w = fma2(z, z, M1);          // z^2 - 1
                sacc[bi][k] = add2(sacc[bi][k], w);   // sum z^2 = sum w + count
                pacc[bi][k] = mul2(pacc[bi][k], w);
            }
        }
    }
}

__global__ __launch_bounds__(TPB, 3)
void wavelet_kernel(const float* __restrict__ x,
                    const float* __restrict__ centers,
                    const float* __restrict__ scales,
                    float* __restrict__ out, int N)
{
    float* sx = smem_dyn;                   // [BT][XSTRIDE]  b-major
    float* sa = sx + BT * XSTRIDE;          // [D][ASTRIDE]   d-major (transposed): 1/s
    float* sb = sa + D_DIM * ASTRIDE;       // [D][ASTRIDE]   -c/s

    const int tid = threadIdx.x;
    const int b0 = blockIdx.x * BT;
    const int n0 = blockIdx.y * NT;

    // x tile (coalesced)
    #pragma unroll 2
    for (int i = tid; i < BT * D_DIM; i += TPB) {
        int r = i >> 6, c = i & 63;
        sx[r * XSTRIDE + c] = x[(b0 + r) * D_DIM + c];
    }
    // a/b tiles, transposed to [d][n]
    #pragma unroll 4
    for (int i = tid; i < NT * D_DIM; i += TPB) {
        int d = i & 63, n = i >> 6;
        int g = (n0 + n) * D_DIM + d;
        float inv = 1.0f / scales[g];
        sa[d * ASTRIDE + n] = inv;
        sb[d * ASTRIDE + n] = -centers[g] * inv;
    }
    __syncthreads();

    const int ng = tid & 15;   // 4 n's at ng*4
    const int bg = tid >> 4;   // 4 b's at bg*4

    const float* xrow = sx + (bg * 4) * XSTRIDE;
    const float* arow = sa + ng * 4;
    const float* brow = sb + ng * 4;

    const uint64_t M1 = pk2(-1.0f, -1.0f);
    uint64_t sacc[4][2], pacc[4][2];
    #pragma unroll
    for (int bi = 0; bi < 4; bi++)
        #pragma unroll
        for (int k = 0; k < 2; k++) { sacc[bi][k] = pk2(0.f, 0.f); pacc[bi][k] = pk2(1.f, 1.f); }

    // first half: d = 0..31
    #pragma unroll 1
    for (int dblk = 0; dblk < 32; dblk += 4)
        do_dblk(xrow, arow, brow, dblk, M1, sacc, pacc);

    // range-control fold: apply Gaussian factor for first 32 dims
    #pragma unroll
    for (int bi = 0; bi < 4; bi++)
        #pragma unroll
        for (int k = 0; k < 2; k++) {
            float s0, s1, p0, p1;
            upk2(sacc[bi][k], s0, s1);
            upk2(pacc[bi][k], p0, p1);
            p0 *= __expf(-0.5f * (s0 + 32.0f));
            p1 *= __expf(-0.5f * (s1 + 32.0f));
            pacc[bi][k] = pk2(p0, p1);
            sacc[bi][k] = pk2(0.f, 0.f);
        }

    // second half: d = 32..63
    #pragma unroll 1
    for (int dblk = 32; dblk < 64; dblk += 4)
        do_dblk(xrow, arow, brow, dblk, M1, sacc, pacc);

    // epilogue
    float* orow = out + (long)(b0 + bg * 4) * N + n0 + ng * 4;
    #pragma unroll
    for (int bi = 0; bi < 4; bi++) {
        float h[4];
        #pragma unroll
        for (int k = 0; k < 2; k++) {
            float s0, s1, p0, p1;
            upk2(sacc[bi][k], s0, s1);
            upk2(pacc[bi][k], p0, p1);
            h[2 * k]     = p0 * __expf(-0.5f * (s0 + 32.0f));
            h[2 * k + 1] = p1 * __expf(-0.5f * (s1 + 32.0f));
        }
        float4 v = {h[0], h[1], h[2], h[3]};
        *reinterpret_cast<float4*>(orow + (long)bi * N) = v;
    }
}

extern "C" void kernel_launch(void* const* d_in, const int* in_sizes, int n_in,
                              void* d_out, int out_size)
{
    const float* x       = (const float*)d_in[0];
    const float* centers = (const float*)d_in[1];
    const float* scales  = (const float*)d_in[2];
    float* out = (float*)d_out;

    const int B = in_sizes[0] / D_DIM;   // 8192
    const int N = in_sizes[1] / D_DIM;   // 512

    const int smem_bytes = (BT * XSTRIDE + 2 * D_DIM * ASTRIDE) * sizeof(float); // 52224
    static bool attr_set = false;
    if (!attr_set) {
        cudaFuncSetAttribute(wavelet_kernel,
                             cudaFuncAttributeMaxDynamicSharedMemorySize, smem_bytes);
        attr_set = true;
    }

    dim3 grid(B / BT, N / NT);           // (128, 8) = 1024 blocks
    wavelet_kernel<<<grid, TPB, smem_bytes>>>(x, centers, scales, out, N);
}